// round 16
// baseline (speedup 1.0000x reference)
#include <cuda_runtime.h>
#include <cuda_fp16.h>
#include <math.h>
#include <stdint.h>

#define SEQ    4096
#define BATCH  4
#define EMB    1024
#define TOKENS (BATCH*SEQ)   /* 16384 */

// ---------------- scratch (static device globals — no allocation) ----------
__device__ float g_q[(size_t)TOKENS*EMB];
__device__ float g_k[(size_t)TOKENS*EMB];
__device__ float g_v[(size_t)TOKENS*EMB];
// A operands: fp16 hi only, tiled chunks [tile][kc] of 8KB: [r(128)][p(4)][16B]
__device__ __half g_xs[(size_t)TOKENS*EMB];
__device__ __half g_as[(size_t)TOKENS*EMB];
// B operands: fp16 hi/lo, tiled chunks [tile][kc][v(2)] of 16KB
__device__ __half g_ws[4][(size_t)2*EMB*EMB];
__device__ float2 g_cs[SEQ*32];              // packed {cos, sin}
__device__ float g_lam;

// ================= PTX helpers (no 'a'-suffix features!) ===================
__device__ __forceinline__ uint32_t smem_u32(const void* p) {
    uint32_t a;
    asm("{ .reg .u64 t; cvta.to.shared.u64 t, %1; cvt.u32.u64 %0, t; }" : "=r"(a) : "l"(p));
    return a;
}
#define MBARRIER_INIT(mb, cnt) \
    asm volatile("mbarrier.init.shared.b64 [%0], %1;" :: "r"((uint32_t)(mb)), "r"((uint32_t)(cnt)) : "memory")
#define MBARRIER_ARRIVE(mb) \
    asm volatile("mbarrier.arrive.shared.b64 _, [%0];" :: "r"((uint32_t)(mb)) : "memory")
#define MBARRIER_EXPECT_TX(mb, bytes) \
    asm volatile("mbarrier.arrive.expect_tx.shared.b64 _, [%0], %1;" \
                 :: "r"((uint32_t)(mb)), "r"((uint32_t)(bytes)) : "memory")
#define MBARRIER_WAIT_PARITY(mb, ph) do { \
    uint32_t _m = (uint32_t)(mb), _p = (uint32_t)(ph), _d; \
    asm volatile("{\n\t.reg .pred p;\n\tmbarrier.try_wait.parity.acquire.cta.shared::cta.b64 p, [%1], %2;\n\tselp.b32 %0, 1, 0, p;\n\t}" \
        : "=r"(_d) : "r"(_m), "r"(_p) : "memory"); \
    if (!_d) { \
        asm volatile("{\n\t.reg .pred P1;\n\tWL_%=:\n\tmbarrier.try_wait.parity.acquire.cta.shared::cta.b64 P1, [%0], %1, 0x989680;\n\t@P1 bra.uni WD_%=;\n\tbra.uni WL_%=;\n\tWD_%=:\n\t}" \
            :: "r"(_m), "r"(_p) : "memory"); \
    } \
} while (0)
#define BULK_G2S(dst, src, bytes, mb) \
    asm volatile("cp.async.bulk.shared::cta.global.mbarrier::complete_tx::bytes [%0], [%1], %2, [%3];" \
        :: "r"((uint32_t)(dst)), "l"(src), "r"((uint32_t)(bytes)), "r"((uint32_t)(mb)) : "memory")
#define LDMX4(r, addr) \
    asm volatile("ldmatrix.sync.aligned.m8n8.x4.shared.b16 {%0,%1,%2,%3}, [%4];" \
        : "=r"((r)[0]), "=r"((r)[1]), "=r"((r)[2]), "=r"((r)[3]) : "r"((uint32_t)(addr)))
#define MMA_F16(d, a, b0, b1) \
    asm volatile("mma.sync.aligned.m16n8k16.row.col.f32.f16.f16.f32 " \
        "{%0,%1,%2,%3}, {%4,%5,%6,%7}, {%8,%9}, {%0,%1,%2,%3};" \
        : "+f"((d)[0]), "+f"((d)[1]), "+f"((d)[2]), "+f"((d)[3]) \
        : "r"((a)[0]), "r"((a)[1]), "r"((a)[2]), "r"((a)[3]), "r"(b0), "r"(b1))
// fp16-accumulator MMA (lo-chain): d/c are 2x .f16x2 regs, same element map
#define MMA_F16ACC(dc, a, b0, b1) \
    asm volatile("mma.sync.aligned.m16n8k16.row.col.f16.f16.f16.f16 " \
        "{%0,%1}, {%2,%3,%4,%5}, {%6,%7}, {%0,%1};" \
        : "+r"((dc)[0]), "+r"((dc)[1]) \
        : "r"((a)[0]), "r"((a)[1]), "r"((a)[2]), "r"((a)[3]), "r"(b0), "r"(b1))

// ---------------- rotary table (double precision for accuracy) -------------
__global__ void rope_table_kernel() {
    int i = blockIdx.x * blockDim.x + threadIdx.x;
    if (i >= SEQ * 32) return;
    int pos = i >> 5, j = i & 31;
    double invf = exp(-((double)(2 * j) / 64.0) * log(10000.0));
    double th = (double)pos * invf;
    g_cs[i] = make_float2((float)cos(th), (float)sin(th));
}

// ---------------- lambda scalar --------------------------------------------
__global__ void lam_kernel(const float* __restrict__ lq1, const float* __restrict__ lk1,
                           const float* __restrict__ lq2, const float* __restrict__ lk2) {
    if (threadIdx.x == 0) {
        double s1 = 0.0, s2 = 0.0;
        for (int i = 0; i < 64; i++) {
            s1 += (double)lq1[i] * (double)lk1[i];
            s2 += (double)lq2[i] * (double)lk2[i];
        }
        double LI = 0.8 - 0.6 * exp(-3.6);
        g_lam = (float)(exp(s1) - exp(s2) + LI);
    }
}

// ---------------- fp32 -> fp16 packing helpers -----------------------------
__device__ __forceinline__ uint32_t hpack(__half a, __half b) {
    __half2 t = __halves2half2(a, b);
    return *(uint32_t*)&t;
}
__device__ __forceinline__ uint4 pack8_hi(const float* vv) {
    uint32_t w[4];
#pragma unroll
    for (int u = 0; u < 4; u++)
        w[u] = hpack(__float2half_rn(vv[2*u]), __float2half_rn(vv[2*u+1]));
    return make_uint4(w[0], w[1], w[2], w[3]);
}
__device__ __forceinline__ void split8_hl(const float* vv, uint4& hv, uint4& lv) {
    uint32_t hw[4], lw[4];
#pragma unroll
    for (int u = 0; u < 4; u++) {
        float x0 = vv[2*u], x1 = vv[2*u+1];
        __half h0 = __float2half_rn(x0), h1 = __float2half_rn(x1);
        __half l0 = __float2half_rn(x0 - __half2float(h0));
        __half l1 = __float2half_rn(x1 - __half2float(h1));
        hw[u] = hpack(h0, h1);
        lw[u] = hpack(l0, l1);
    }
    hv = make_uint4(hw[0], hw[1], hw[2], hw[3]);
    lv = make_uint4(lw[0], lw[1], lw[2], lw[3]);
}

// A-side: x [M,1024] fp32 -> tiled fp16-hi chunks (pre-swizzled, 8KB/chunk)
__global__ void split_x_kernel(const float* __restrict__ in, __half* __restrict__ outp) {
    int i = blockIdx.x * blockDim.x + threadIdx.x;   // TOKENS*128
    int row = i >> 7, kg = i & 127;
    const float4* src = (const float4*)(in + (size_t)row * EMB + kg * 8);
    float4 v0 = src[0], v1 = src[1];
    float vv[8] = {v0.x, v0.y, v0.z, v0.w, v1.x, v1.y, v1.z, v1.w};
    uint4 hv = pack8_hi(vv);
    int tile = row >> 7, r = row & 127;
    int kc = kg >> 2, c = kg & 3, p = c ^ ((r >> 1) & 3);
    size_t base = (size_t)(tile * 32 + kc) * 8192 + (size_t)r * 64 + p * 16;
    *(uint4*)((char*)outp + base) = hv;
}

// W [K,N] -> transposed [N,K] tiled fp16 hi/lo chunks (16KB/chunk)
// grid.z = 0..3 selects among the four weight matrices (single launch).
__global__ void wsplit4_kernel(const float* __restrict__ W0, const float* __restrict__ W1,
                               const float* __restrict__ W2, const float* __restrict__ W3,
                               __half* __restrict__ outp) {
    __shared__ float t[32][33];
    int zi = blockIdx.z;
    const float* W = (zi == 0) ? W0 : (zi == 1) ? W1 : (zi == 2) ? W2 : W3;
    __half* out = outp + (size_t)zi * 2 * EMB * EMB;
    int bn = blockIdx.x * 32, bk = blockIdx.y * 32;
    int tid = threadIdx.x;  // 128
#pragma unroll
    for (int j = 0; j < 8; j++) {
        int idx = tid + 128 * j;
        int kl = idx >> 5, nl = idx & 31;
        t[nl][kl] = W[(size_t)(bk + kl) * EMB + bn + nl];
    }
    __syncthreads();
    int nl = tid >> 2, kg = tid & 3;
    float vv[8];
#pragma unroll
    for (int e = 0; e < 8; e++) vv[e] = t[nl][kg * 8 + e];
    uint4 hv, lv;
    split8_hl(vv, hv, lv);
    int n = bn + nl;
    int tile = n >> 7, r = n & 127;
    int kc = bk >> 5, c = kg, p = c ^ ((r >> 1) & 3);
    size_t base = (size_t)(tile * 32 + kc) * 16384 + (size_t)r * 64 + p * 16;
    *(uint4*)((char*)out + base)        = hv;
    *(uint4*)((char*)out + base + 8192) = lv;
}

// ---------------- HMMA GEMM: C[M,1024] = A @ B^T, fp16x2 compensation ------
// D = Ah*Bh (fp32 acc) + Ah*Bl (fp16 acc, combined in epilogue).
// Tiles BM=BN=128, BK=64; 8 warps (2m x 4n), warp tile 64x32.
// Stage = 16KB A + 32KB B via cp.async.bulk; NST=4, 1 CTA/SM.
// Fragment double-buffering: ks+1 fragments loaded before ks's MMAs issue.
#define NST 4
#define STAGE_BYTES 49152
#define SMEM_DYN (1024 + NST*STAGE_BYTES)   /* 197632 B */

__global__ __launch_bounds__(256, 1)
void gemm_hmma(const __half* __restrict__ As,
               const __half* __restrict__ Bs,
               float* __restrict__ C0, float* __restrict__ C1, float* __restrict__ C2) {
    extern __shared__ __align__(1024) char smem[];
    uint32_t sb = smem_u32(smem);
    int tid = threadIdx.x, wid = tid >> 5, lane = tid & 31;
    int warp_m = wid & 1, warp_n = wid >> 1;   // 2m x 4n, warp tile 64x32
    int tile_m = blockIdx.y, tile_n = blockIdx.x;
    int z = blockIdx.z;
    float* C = (z == 0) ? C0 : (z == 1) ? C1 : C2;

    if (tid == 0) {
        for (int s = 0; s < NST; s++) {
            MBARRIER_INIT(sb + 64 * s, 1);          // full[s]: tx-based
            MBARRIER_INIT(sb + 512 + 64 * s, 8);    // empty[s]: 8 warp arrives
        }
    }
    __syncthreads();

    const char* Abase = (const char*)As + (size_t)tile_m * 32 * 8192;
    const char* Bbase = (const char*)Bs + (size_t)z * 4194304 + (size_t)tile_n * 32 * 16384;

    if (tid == 0) {
#pragma unroll
        for (int s = 0; s < NST; s++) {
            MBARRIER_EXPECT_TX(sb + 64 * s, STAGE_BYTES);
            BULK_G2S(sb + 1024 + s * STAGE_BYTES,         Abase + (size_t)s * 16384, 16384, sb + 64 * s);
            BULK_G2S(sb + 1024 + s * STAGE_BYTES + 16384, Bbase + (size_t)s * 32768, 32768, sb + 64 * s);
        }
    }

    // lane constants (ldmatrix addressing)
    int q = lane >> 3, rr = lane & 7;
    int a_rlow  = ((q & 1) << 3) + rr;           // row within m16 tile
    int a_sel   = (a_rlow >> 1) & 3;
    int a_chalf = q >> 1;                         // k-half (0/1)
    uint32_t a_off = (uint32_t)((warp_m * 64 + a_rlow) * 64);
    int b_rlow  = ((q >> 1) << 3) + rr;          // row (n) within n16 group
    int b_sel   = (b_rlow >> 1) & 3;
    int b_chalf = q & 1;
    uint32_t b_off = (uint32_t)((warp_n * 32 + b_rlow) * 64);

    float acc[4][4][4];       // [mt][n8][4] — hi chain, fp32
    uint32_t accl[4][4][2];   // [mt][n8][2] — lo chain, fp16x2 pairs
#pragma unroll
    for (int i = 0; i < 4; i++)
#pragma unroll
        for (int j = 0; j < 4; j++) {
#pragma unroll
            for (int u = 0; u < 4; u++) acc[i][j][u] = 0.0f;
            accl[i][j][0] = 0u; accl[i][j][1] = 0u;
        }

    // double-buffered fragments
    uint32_t fa[2][4][4];     // [buf][mtile][4]
    uint32_t fbh[2][2][4];    // [buf][p4][4]
    uint32_t fbl[2][2][4];

#define LOAD_FRAGS(ksv, buf) do { \
        int _kcs = (ksv) >> 1, _kh = (ksv) & 1; \
        uint32_t _a_st = st + _kcs * 8192; \
        uint32_t _b_st = st + 16384 + _kcs * 16384; \
        uint32_t _a_unit = (uint32_t)((2 * _kh + a_chalf) ^ a_sel) << 4; \
        uint32_t _b_unit = (uint32_t)((2 * _kh + b_chalf) ^ b_sel) << 4; \
        _Pragma("unroll") \
        for (int _mt = 0; _mt < 4; _mt++) \
            LDMX4(fa[buf][_mt], _a_st + a_off + _mt * 1024 + _a_unit); \
        _Pragma("unroll") \
        for (int _p4 = 0; _p4 < 2; _p4++) { \
            uint32_t _ba = _b_st + b_off + _p4 * 1024 + _b_unit; \
            LDMX4(fbh[buf][_p4], _ba); \
            LDMX4(fbl[buf][_p4], _ba + 8192); \
        } \
    } while (0)

    for (int it = 0; it < 16; it++) {
        int s = it & (NST - 1);
        MBARRIER_WAIT_PARITY(sb + 64 * s, (it >> 2) & 1);
        uint32_t st = sb + 1024 + s * STAGE_BYTES;
        LOAD_FRAGS(0, 0);
#pragma unroll
        for (int ks = 0; ks < 4; ks++) {
            int cur = ks & 1, nxt = cur ^ 1;
            if (ks < 3) LOAD_FRAGS(ks + 1, nxt);
#pragma unroll
            for (int p4 = 0; p4 < 2; p4++)
#pragma unroll
                for (int mt = 0; mt < 4; mt++)
#pragma unroll
                    for (int nt = 0; nt < 2; nt++) {
                        int nn = p4 * 2 + nt;
                        MMA_F16(acc[mt][nn], fa[cur][mt],
                                fbh[cur][p4][nt * 2], fbh[cur][p4][nt * 2 + 1]);
                        MMA_F16ACC(accl[mt][nn], fa[cur][mt],
                                   fbl[cur][p4][nt * 2], fbl[cur][p4][nt * 2 + 1]);
                    }
        }
        // consumer-release: this warp is done reading stage s
        __syncwarp();
        if (lane == 0) MBARRIER_ARRIVE(sb + 512 + 64 * s);
        // producer: refetch stage s for chunk it+NST once all 8 warps released
        if (tid == 0 && it + NST < 16) {
            MBARRIER_WAIT_PARITY(sb + 512 + 64 * s, (it >> 2) & 1);
            int c2 = it + NST;
            MBARRIER_EXPECT_TX(sb + 64 * s, STAGE_BYTES);
            BULK_G2S(st,         Abase + (size_t)c2 * 16384, 16384, sb + 64 * s);
            BULK_G2S(st + 16384, Bbase + (size_t)c2 * 32768, 32768, sb + 64 * s);
        }
    }
#undef LOAD_FRAGS

    // epilogue: combine hi + lo chains, fragment -> global (row-major C)
    int row0 = tile_m * 128 + warp_m * 64 + (lane >> 2);
    int col0 = tile_n * 128 + warp_n * 32 + ((lane & 3) << 1);
#pragma unroll
    for (int mt = 0; mt < 4; mt++)
#pragma unroll
        for (int n8 = 0; n8 < 4; n8++) {
            float* d = acc[mt][n8];
            float2 l01 = __half22float2(*(__half2*)&accl[mt][n8][0]);
            float2 l23 = __half22float2(*(__half2*)&accl[mt][n8][1]);
            *(float2*)(C + (size_t)(row0 + mt * 16)     * EMB + col0 + n8 * 8) =
                make_float2(d[0] + l01.x, d[1] + l01.y);
            *(float2*)(C + (size_t)(row0 + mt * 16 + 8) * EMB + col0 + n8 * 8) =
                make_float2(d[2] + l23.x, d[3] + l23.y);
        }
}

// ------- fused diff-attention: persistent, bulk-pipelined -------------------
// Each CTA owns 16 tokens, processes 2 per iteration (256 threads), with
// double-buffered cp.async.bulk prefetch of q/k/v (24KB/stage) — DRAM latency
// hidden behind compute. Rotary applied in-place in smem (identical FMA
// sequence as before -> bit-identical results).
#define DIFF_TPB 16
#define DIFF_IT  (DIFF_TPB/2)
#define DIFF_BUF 24576
#define SMEM_DIFF (1024 + 2*DIFF_BUF + 1024)   /* 51200 B */

__global__ __launch_bounds__(256)
void diffattn_kernel(const float* __restrict__ lnw, const float* __restrict__ lnb,
                     __half* __restrict__ outp) {
    extern __shared__ __align__(1024) char dsm[];
    uint32_t sb = smem_u32(dsm);
    int tidx = threadIdx.x;
    int tt = tidx >> 7, tid = tidx & 127;
    int base = blockIdx.x * DIFF_TPB;
    float* saw = (float*)(dsm + 1024 + 2 * DIFF_BUF);   // [tt][sub][64]

    if (tidx == 0) {
        MBARRIER_INIT(sb + 0, 1);
        MBARRIER_INIT(sb + 64, 1);
    }
    __syncthreads();

    if (tidx == 0) {   // initial fill: buffer 0 <- tokens base, base+1
        size_t off = (size_t)base * 4096;
        MBARRIER_EXPECT_TX(sb + 0, DIFF_BUF);
        BULK_G2S(sb + 1024,         (const char*)g_q + off, 8192, sb + 0);
        BULK_G2S(sb + 1024 + 8192,  (const char*)g_k + off, 8192, sb + 0);
        BULK_G2S(sb + 1024 + 16384, (const char*)g_v + off, 8192, sb + 0);
    }

    float lam = g_lam;
    const float LIC = 0.21639423346837556f;  // 1 - LAMBDA_INIT

    for (int i = 0; i < DIFF_IT; i++) {
        int b = i & 1;
        // prefetch next pair into the other buffer (consumed in iter i-1,
        // end-of-iteration __syncthreads guarantees it's free)
        if (tidx == 0 && i + 1 < DIFF_IT) {
            int nb = (i + 1) & 1;
            uint32_t d = sb + 1024 + nb * DIFF_BUF;
            size_t off = (size_t)(base + 2 * (i + 1)) * 4096;
            MBARRIER_EXPECT_TX(sb + 64 * nb, DIFF_BUF);
            BULK_G2S(d,         (const char*)g_q + off, 8192, sb + 64 * nb);
            BULK_G2S(d + 8192,  (const char*)g_k + off, 8192, sb + 64 * nb);
            BULK_G2S(d + 16384, (const char*)g_v + off, 8192, sb + 64 * nb);
        }
        MBARRIER_WAIT_PARITY(sb + 64 * b, (i >> 1) & 1);

        int t = base + 2 * i + tt;
        int pos = t & (SEQ - 1);
        char* buf = dsm + 1024 + b * DIFF_BUF;
        float* sq = (float*)(buf + tt * 4096);
        float* sk = (float*)(buf + 8192 + tt * 4096);
        float* sv = (float*)(buf + 16384 + tt * 4096);

        // in-place rotary on q,k (identical formula/order as before)
#pragma unroll
        for (int r = 0; r < 2; r++) {
            int ii = tid + 128 * r;
            int j0 = (2 * ii) & 31;
            float4 cs4 = *(const float4*)&g_cs[pos * 32 + j0];  // {c0,s0,c1,s1}
            float4 vq = ((float4*)sq)[ii], vk = ((float4*)sk)[ii];
            float4 oq, ok;
            oq.x = vq.x * cs4.x - vq.y * cs4.y;  oq.y = vq.y * cs4.x + vq.x * cs4.y;
            oq.z = vq.z * cs4.z - vq.w * cs4.w;  oq.w = vq.w * cs4.z + vq.z * cs4.w;
            ok.x = vk.x * cs4.x - vk.y * cs4.y;  ok.y = vk.y * cs4.x + vk.x * cs4.y;
            ok.z = vk.z * cs4.z - vk.w * cs4.w;  ok.w = vk.w * cs4.z + vk.z * cs4.w;
            ((float4*)sq)[ii] = oq;
            ((float4*)sk)[ii] = ok;
        }
        __syncthreads();

        // scores + softmax over heads: 2 subs x 8 n x 8 m (per token slot)
        {
            int sub = tid >> 6;
            int n   = (tid >> 3) & 7;
            int m   = tid & 7;
            const float* qrow = sq + n * 128 + sub * 64;
            const float* krow = sk + m * 128 + sub * 64;
            float s = 0.0f;
#pragma unroll
            for (int d4 = 0; d4 < 16; d4++) {
                float4 q4 = *(const float4*)(qrow + 4 * d4);
                float4 k4 = *(const float4*)(krow + 4 * d4);
                s += q4.x * k4.x + q4.y * k4.y + q4.z * k4.z + q4.w * k4.w;
            }
            s *= 0.35355339059327376f;
            float mx = s;
            mx = fmaxf(mx, __shfl_xor_sync(0xffffffffu, mx, 1));
            mx = fmaxf(mx, __shfl_xor_sync(0xffffffffu, mx, 2));
            mx = fmaxf(mx, __shfl_xor_sync(0xffffffffu, mx, 4));
            float p = expf(s - mx);
            float sum = p;
            sum += __shfl_xor_sync(0xffffffffu, sum, 1);
            sum += __shfl_xor_sync(0xffffffffu, sum, 2);
            sum += __shfl_xor_sync(0xffffffffu, sum, 4);
            saw[tt * 128 + sub * 64 + n * 8 + m] = p / sum;
        }
        __syncthreads();

        // output: thread owns 8 contiguous dims of head n
        int n   = tid >> 4;
        int off = (tid & 15) * 8;
        float o1[8] = {0,0,0,0,0,0,0,0}, o2[8] = {0,0,0,0,0,0,0,0};
#pragma unroll
        for (int m = 0; m < 8; m++) {
            float w1 = saw[tt * 128 + 0 * 64 + n * 8 + m];
            float w2 = saw[tt * 128 + 1 * 64 + n * 8 + m];
            float4 va = *(const float4*)&sv[m * 128 + off];
            float4 vb = *(const float4*)&sv[m * 128 + off + 4];
            o1[0] += w1 * va.x; o1[1] += w1 * va.y; o1[2] += w1 * va.z; o1[3] += w1 * va.w;
            o1[4] += w1 * vb.x; o1[5] += w1 * vb.y; o1[6] += w1 * vb.z; o1[7] += w1 * vb.w;
            o2[0] += w2 * va.x; o2[1] += w2 * va.y; o2[2] += w2 * va.z; o2[3] += w2 * va.w;
            o2[4] += w2 * vb.x; o2[5] += w2 * vb.y; o2[6] += w2 * vb.z; o2[7] += w2 * vb.w;
        }
        float a[8];
#pragma unroll
        for (int u = 0; u < 8; u++) a[u] = o1[u] - lam * o2[u];

        float ss = 0.0f;
#pragma unroll
        for (int u = 0; u < 8; u++) ss += a[u] * a[u];
        ss += __shfl_xor_sync(0xffffffffu, ss, 1);
        ss += __shfl_xor_sync(0xffffffffu, ss, 2);
        ss += __shfl_xor_sync(0xffffffffu, ss, 4);
        ss += __shfl_xor_sync(0xffffffffu, ss, 8);
        float rms = rsqrtf(ss * (1.0f / 128.0f) + 1e-8f);

        float vals[8];
#pragma unroll
        for (int u = 0; u < 8; u++)
            vals[u] = (a[u] * rms * lnw[off + u] + lnb[off + u]) * LIC;

        uint4 hv = pack8_hi(vals);
        int e0w = n * 128 + off;
        int tile = t >> 7, r = t & 127;
        int kc = e0w >> 5, c4 = (e0w >> 3) & 3, p = c4 ^ ((r >> 1) & 3);
        size_t obase = (size_t)(tile * 32 + kc) * 8192 + (size_t)r * 64 + p * 16;
        *(uint4*)((char*)outp + obase) = hv;

        __syncthreads();   // buffer b free for the prefetch at iter i+1
    }
}

// ---------------- launch ----------------------------------------------------
extern "C" void kernel_launch(void* const* d_in, const int* in_sizes, int n_in,
                              void* d_out, int out_size) {
    const float* x   = (const float*)d_in[0];
    const float* Wq  = (const float*)d_in[1];
    const float* Wk  = (const float*)d_in[2];
    const float* Wv  = (const float*)d_in[3];
    const float* Wo  = (const float*)d_in[4];
    const float* lq1 = (const float*)d_in[5];
    const float* lk1 = (const float*)d_in[6];
    const float* lq2 = (const float*)d_in[7];
    const float* lk2 = (const float*)d_in[8];
    const float* lnw = (const float*)d_in[9];
    const float* lnb = (const float*)d_in[10];
    float* out = (float*)d_out;

    __half *xs, *as, *ws;
    cudaGetSymbolAddress((void**)&xs, g_xs);
    cudaGetSymbolAddress((void**)&as, g_as);
    cudaGetSymbolAddress((void**)&ws, g_ws);
    float *q, *k, *v;
    cudaGetSymbolAddress((void**)&q,  g_q);
    cudaGetSymbolAddress((void**)&k,  g_k);
    cudaGetSymbolAddress((void**)&v,  g_v);

    cudaFuncSetAttribute(gemm_hmma, cudaFuncAttributeMaxDynamicSharedMemorySize, SMEM_DYN);
    cudaFuncSetAttribute(diffattn_kernel, cudaFuncAttributeMaxDynamicSharedMemorySize, SMEM_DIFF);

    rope_table_kernel<<<512, 256>>>();                                   // 1
    lam_kernel<<<1, 32>>>(lq1, lk1, lq2, lk2);                           // 2
    split_x_kernel<<<TOKENS * 128 / 256, 256>>>(x, xs);                  // 3
    wsplit4_kernel<<<dim3(32, 32, 4), 128>>>(Wq, Wk, Wv, Wo, ws);        // 4

    // fused QKV GEMM (z selects weight + destination)
    dim3 g3(EMB / 128, TOKENS / 128, 3);
    gemm_hmma<<<g3, 256, SMEM_DYN>>>(xs, ws, q, k, v);

    // fused rotary + diff-attention + RMSNorm + fp16 pack (persistent, piped)
    diffattn_kernel<<<TOKENS / DIFF_TPB, 256, SMEM_DIFF>>>(lnw, lnb, as);

    // output projection
    dim3 g1(EMB / 128, TOKENS / 128, 1);
    gemm_hmma<<<g1, 256, SMEM_DYN>>>(as, ws + 3ull * 2 * EMB * EMB, out, out, out);
}

// round 17
// speedup vs baseline: 1.0253x; 1.0253x over previous
#include <cuda_runtime.h>
#include <cuda_fp16.h>
#include <math.h>
#include <stdint.h>

#define SEQ    4096
#define BATCH  4
#define EMB    1024
#define TOKENS (BATCH*SEQ)   /* 16384 */

// ---------------- scratch (static device globals — no allocation) ----------
__device__ float g_q[(size_t)TOKENS*EMB];
__device__ float g_k[(size_t)TOKENS*EMB];
__device__ float g_v[(size_t)TOKENS*EMB];
// A operands: fp16 hi only, tiled chunks [tile][kc] of 8KB: [r(128)][p(4)][16B]
__device__ __half g_xs[(size_t)TOKENS*EMB];
__device__ __half g_as[(size_t)TOKENS*EMB];
// B operands: fp16 hi/lo, tiled chunks [tile][kc][v(2)] of 16KB
__device__ __half g_ws[4][(size_t)2*EMB*EMB];
__device__ float2 g_cs[SEQ*32];              // packed {cos, sin}
__device__ float g_lam;

// ================= PTX helpers (no 'a'-suffix features!) ===================
__device__ __forceinline__ uint32_t smem_u32(const void* p) {
    uint32_t a;
    asm("{ .reg .u64 t; cvta.to.shared.u64 t, %1; cvt.u32.u64 %0, t; }" : "=r"(a) : "l"(p));
    return a;
}
#define MBARRIER_INIT(mb, cnt) \
    asm volatile("mbarrier.init.shared.b64 [%0], %1;" :: "r"((uint32_t)(mb)), "r"((uint32_t)(cnt)) : "memory")
#define MBARRIER_ARRIVE(mb) \
    asm volatile("mbarrier.arrive.shared.b64 _, [%0];" :: "r"((uint32_t)(mb)) : "memory")
#define MBARRIER_EXPECT_TX(mb, bytes) \
    asm volatile("mbarrier.arrive.expect_tx.shared.b64 _, [%0], %1;" \
                 :: "r"((uint32_t)(mb)), "r"((uint32_t)(bytes)) : "memory")
#define MBARRIER_WAIT_PARITY(mb, ph) do { \
    uint32_t _m = (uint32_t)(mb), _p = (uint32_t)(ph), _d; \
    asm volatile("{\n\t.reg .pred p;\n\tmbarrier.try_wait.parity.acquire.cta.shared::cta.b64 p, [%1], %2;\n\tselp.b32 %0, 1, 0, p;\n\t}" \
        : "=r"(_d) : "r"(_m), "r"(_p) : "memory"); \
    if (!_d) { \
        asm volatile("{\n\t.reg .pred P1;\n\tWL_%=:\n\tmbarrier.try_wait.parity.acquire.cta.shared::cta.b64 P1, [%0], %1, 0x989680;\n\t@P1 bra.uni WD_%=;\n\tbra.uni WL_%=;\n\tWD_%=:\n\t}" \
            :: "r"(_m), "r"(_p) : "memory"); \
    } \
} while (0)
#define BULK_G2S(dst, src, bytes, mb) \
    asm volatile("cp.async.bulk.shared::cta.global.mbarrier::complete_tx::bytes [%0], [%1], %2, [%3];" \
        :: "r"((uint32_t)(dst)), "l"(src), "r"((uint32_t)(bytes)), "r"((uint32_t)(mb)) : "memory")
#define LDMX4(r, addr) \
    asm volatile("ldmatrix.sync.aligned.m8n8.x4.shared.b16 {%0,%1,%2,%3}, [%4];" \
        : "=r"((r)[0]), "=r"((r)[1]), "=r"((r)[2]), "=r"((r)[3]) : "r"((uint32_t)(addr)))
#define MMA_F16(d, a, b0, b1) \
    asm volatile("mma.sync.aligned.m16n8k16.row.col.f32.f16.f16.f32 " \
        "{%0,%1,%2,%3}, {%4,%5,%6,%7}, {%8,%9}, {%0,%1,%2,%3};" \
        : "+f"((d)[0]), "+f"((d)[1]), "+f"((d)[2]), "+f"((d)[3]) \
        : "r"((a)[0]), "r"((a)[1]), "r"((a)[2]), "r"((a)[3]), "r"(b0), "r"(b1))
// fp16-accumulator MMA (lo-chain): d/c are 2x .f16x2 regs, same element map
#define MMA_F16ACC(dc, a, b0, b1) \
    asm volatile("mma.sync.aligned.m16n8k16.row.col.f16.f16.f16.f16 " \
        "{%0,%1}, {%2,%3,%4,%5}, {%6,%7}, {%0,%1};" \
        : "+r"((dc)[0]), "+r"((dc)[1]) \
        : "r"((a)[0]), "r"((a)[1]), "r"((a)[2]), "r"((a)[3]), "r"(b0), "r"(b1))

// ---------------- fp32 -> fp16 packing helpers -----------------------------
__device__ __forceinline__ uint32_t hpack(__half a, __half b) {
    __half2 t = __halves2half2(a, b);
    return *(uint32_t*)&t;
}
__device__ __forceinline__ uint4 pack8_hi(const float* vv) {
    uint32_t w[4];
#pragma unroll
    for (int u = 0; u < 4; u++)
        w[u] = hpack(__float2half_rn(vv[2*u]), __float2half_rn(vv[2*u+1]));
    return make_uint4(w[0], w[1], w[2], w[3]);
}
__device__ __forceinline__ void split8_hl(const float* vv, uint4& hv, uint4& lv) {
    uint32_t hw[4], lw[4];
#pragma unroll
    for (int u = 0; u < 4; u++) {
        float x0 = vv[2*u], x1 = vv[2*u+1];
        __half h0 = __float2half_rn(x0), h1 = __float2half_rn(x1);
        __half l0 = __float2half_rn(x0 - __half2float(h0));
        __half l1 = __float2half_rn(x1 - __half2float(h1));
        hw[u] = hpack(h0, h1);
        lw[u] = hpack(l0, l1);
    }
    hv = make_uint4(hw[0], hw[1], hw[2], hw[3]);
    lv = make_uint4(lw[0], lw[1], lw[2], lw[3]);
}

// ---------------- merged prep: split_x + rope table + lambda ----------------
// Each thread does one split_x unit (TOKENS*128 total). Threads with
// gid < SEQ*32 additionally fill the rope cos/sin table (double precision).
// Block 0 / thread 0 computes lambda. All outputs feed LATER launches only.
__global__ void prep_kernel(const float* __restrict__ in, __half* __restrict__ outp,
                            const float* __restrict__ lq1, const float* __restrict__ lk1,
                            const float* __restrict__ lq2, const float* __restrict__ lk2) {
    int i = blockIdx.x * blockDim.x + threadIdx.x;   // TOKENS*128

    // split_x work
    int row = i >> 7, kg = i & 127;
    const float4* src = (const float4*)(in + (size_t)row * EMB + kg * 8);
    float4 v0 = src[0], v1 = src[1];
    float vv[8] = {v0.x, v0.y, v0.z, v0.w, v1.x, v1.y, v1.z, v1.w};
    uint4 hv = pack8_hi(vv);
    int tile = row >> 7, r = row & 127;
    int kc = kg >> 2, c = kg & 3, p = c ^ ((r >> 1) & 3);
    size_t base = (size_t)(tile * 32 + kc) * 8192 + (size_t)r * 64 + p * 16;
    *(uint4*)((char*)outp + base) = hv;

    // rope table (first SEQ*32 = 131072 threads)
    if (i < SEQ * 32) {
        int pos = i >> 5, j = i & 31;
        double invf = exp(-((double)(2 * j) / 64.0) * log(10000.0));
        double th = (double)pos * invf;
        g_cs[i] = make_float2((float)cos(th), (float)sin(th));
    }

    // lambda (one thread)
    if (i == 0) {
        double s1 = 0.0, s2 = 0.0;
        for (int u = 0; u < 64; u++) {
            s1 += (double)lq1[u] * (double)lk1[u];
            s2 += (double)lq2[u] * (double)lk2[u];
        }
        double LI = 0.8 - 0.6 * exp(-3.6);
        g_lam = (float)(exp(s1) - exp(s2) + LI);
    }
}

// W [K,N] -> transposed [N,K] tiled fp16 hi/lo chunks (16KB/chunk)
// grid.z = 0..3 selects among the four weight matrices (single launch).
__global__ void wsplit4_kernel(const float* __restrict__ W0, const float* __restrict__ W1,
                               const float* __restrict__ W2, const float* __restrict__ W3,
                               __half* __restrict__ outp) {
    __shared__ float t[32][33];
    int zi = blockIdx.z;
    const float* W = (zi == 0) ? W0 : (zi == 1) ? W1 : (zi == 2) ? W2 : W3;
    __half* out = outp + (size_t)zi * 2 * EMB * EMB;
    int bn = blockIdx.x * 32, bk = blockIdx.y * 32;
    int tid = threadIdx.x;  // 128
#pragma unroll
    for (int j = 0; j < 8; j++) {
        int idx = tid + 128 * j;
        int kl = idx >> 5, nl = idx & 31;
        t[nl][kl] = W[(size_t)(bk + kl) * EMB + bn + nl];
    }
    __syncthreads();
    int nl = tid >> 2, kg = tid & 3;
    float vv[8];
#pragma unroll
    for (int e = 0; e < 8; e++) vv[e] = t[nl][kg * 8 + e];
    uint4 hv, lv;
    split8_hl(vv, hv, lv);
    int n = bn + nl;
    int tile = n >> 7, r = n & 127;
    int kc = bk >> 5, c = kg, p = c ^ ((r >> 1) & 3);
    size_t base = (size_t)(tile * 32 + kc) * 16384 + (size_t)r * 64 + p * 16;
    *(uint4*)((char*)out + base)        = hv;
    *(uint4*)((char*)out + base + 8192) = lv;
}

// ---------------- HMMA GEMM: C[M,1024] = A @ B^T, fp16x2 compensation ------
// D = Ah*Bh (fp32 acc) + Ah*Bl (fp16 acc, combined in epilogue).
// Tiles BM=BN=128, BK=64; 8 warps (2m x 4n), warp tile 64x32.
// Stage = 16KB A + 32KB B via cp.async.bulk; NST=4, 1 CTA/SM.
// Fragment double-buffering: ks+1 fragments loaded before ks's MMAs issue.
#define NST 4
#define STAGE_BYTES 49152
#define SMEM_DYN (1024 + NST*STAGE_BYTES)   /* 197632 B */

__global__ __launch_bounds__(256, 1)
void gemm_hmma(const __half* __restrict__ As,
               const __half* __restrict__ Bs,
               float* __restrict__ C0, float* __restrict__ C1, float* __restrict__ C2) {
    extern __shared__ __align__(1024) char smem[];
    uint32_t sb = smem_u32(smem);
    int tid = threadIdx.x, wid = tid >> 5, lane = tid & 31;
    int warp_m = wid & 1, warp_n = wid >> 1;   // 2m x 4n, warp tile 64x32
    int tile_m = blockIdx.y, tile_n = blockIdx.x;
    int z = blockIdx.z;
    float* C = (z == 0) ? C0 : (z == 1) ? C1 : C2;

    if (tid == 0) {
        for (int s = 0; s < NST; s++) {
            MBARRIER_INIT(sb + 64 * s, 1);          // full[s]: tx-based
            MBARRIER_INIT(sb + 512 + 64 * s, 8);    // empty[s]: 8 warp arrives
        }
    }
    __syncthreads();

    const char* Abase = (const char*)As + (size_t)tile_m * 32 * 8192;
    const char* Bbase = (const char*)Bs + (size_t)z * 4194304 + (size_t)tile_n * 32 * 16384;

    if (tid == 0) {
#pragma unroll
        for (int s = 0; s < NST; s++) {
            MBARRIER_EXPECT_TX(sb + 64 * s, STAGE_BYTES);
            BULK_G2S(sb + 1024 + s * STAGE_BYTES,         Abase + (size_t)s * 16384, 16384, sb + 64 * s);
            BULK_G2S(sb + 1024 + s * STAGE_BYTES + 16384, Bbase + (size_t)s * 32768, 32768, sb + 64 * s);
        }
    }

    // lane constants (ldmatrix addressing)
    int q = lane >> 3, rr = lane & 7;
    int a_rlow  = ((q & 1) << 3) + rr;           // row within m16 tile
    int a_sel   = (a_rlow >> 1) & 3;
    int a_chalf = q >> 1;                         // k-half (0/1)
    uint32_t a_off = (uint32_t)((warp_m * 64 + a_rlow) * 64);
    int b_rlow  = ((q >> 1) << 3) + rr;          // row (n) within n16 group
    int b_sel   = (b_rlow >> 1) & 3;
    int b_chalf = q & 1;
    uint32_t b_off = (uint32_t)((warp_n * 32 + b_rlow) * 64);

    float acc[4][4][4];       // [mt][n8][4] — hi chain, fp32
    uint32_t accl[4][4][2];   // [mt][n8][2] — lo chain, fp16x2 pairs
#pragma unroll
    for (int i = 0; i < 4; i++)
#pragma unroll
        for (int j = 0; j < 4; j++) {
#pragma unroll
            for (int u = 0; u < 4; u++) acc[i][j][u] = 0.0f;
            accl[i][j][0] = 0u; accl[i][j][1] = 0u;
        }

    // double-buffered fragments
    uint32_t fa[2][4][4];     // [buf][mtile][4]
    uint32_t fbh[2][2][4];    // [buf][p4][4]
    uint32_t fbl[2][2][4];

#define LOAD_FRAGS(ksv, buf) do { \
        int _kcs = (ksv) >> 1, _kh = (ksv) & 1; \
        uint32_t _a_st = st + _kcs * 8192; \
        uint32_t _b_st = st + 16384 + _kcs * 16384; \
        uint32_t _a_unit = (uint32_t)((2 * _kh + a_chalf) ^ a_sel) << 4; \
        uint32_t _b_unit = (uint32_t)((2 * _kh + b_chalf) ^ b_sel) << 4; \
        _Pragma("unroll") \
        for (int _mt = 0; _mt < 4; _mt++) \
            LDMX4(fa[buf][_mt], _a_st + a_off + _mt * 1024 + _a_unit); \
        _Pragma("unroll") \
        for (int _p4 = 0; _p4 < 2; _p4++) { \
            uint32_t _ba = _b_st + b_off + _p4 * 1024 + _b_unit; \
            LDMX4(fbh[buf][_p4], _ba); \
            LDMX4(fbl[buf][_p4], _ba + 8192); \
        } \
    } while (0)

    for (int it = 0; it < 16; it++) {
        int s = it & (NST - 1);
        MBARRIER_WAIT_PARITY(sb + 64 * s, (it >> 2) & 1);
        uint32_t st = sb + 1024 + s * STAGE_BYTES;
        LOAD_FRAGS(0, 0);
#pragma unroll
        for (int ks = 0; ks < 4; ks++) {
            int cur = ks & 1, nxt = cur ^ 1;
            if (ks < 3) LOAD_FRAGS(ks + 1, nxt);
#pragma unroll
            for (int p4 = 0; p4 < 2; p4++)
#pragma unroll
                for (int mt = 0; mt < 4; mt++)
#pragma unroll
                    for (int nt = 0; nt < 2; nt++) {
                        int nn = p4 * 2 + nt;
                        MMA_F16(acc[mt][nn], fa[cur][mt],
                                fbh[cur][p4][nt * 2], fbh[cur][p4][nt * 2 + 1]);
                        MMA_F16ACC(accl[mt][nn], fa[cur][mt],
                                   fbl[cur][p4][nt * 2], fbl[cur][p4][nt * 2 + 1]);
                    }
        }
        // consumer-release: this warp is done reading stage s
        __syncwarp();
        if (lane == 0) MBARRIER_ARRIVE(sb + 512 + 64 * s);
        // producer: refetch stage s for chunk it+NST once all 8 warps released
        if (tid == 0 && it + NST < 16) {
            MBARRIER_WAIT_PARITY(sb + 512 + 64 * s, (it >> 2) & 1);
            int c2 = it + NST;
            MBARRIER_EXPECT_TX(sb + 64 * s, STAGE_BYTES);
            BULK_G2S(st,         Abase + (size_t)c2 * 16384, 16384, sb + 64 * s);
            BULK_G2S(st + 16384, Bbase + (size_t)c2 * 32768, 32768, sb + 64 * s);
        }
    }
#undef LOAD_FRAGS

    // epilogue: combine hi + lo chains, fragment -> global (row-major C)
    int row0 = tile_m * 128 + warp_m * 64 + (lane >> 2);
    int col0 = tile_n * 128 + warp_n * 32 + ((lane & 3) << 1);
#pragma unroll
    for (int mt = 0; mt < 4; mt++)
#pragma unroll
        for (int n8 = 0; n8 < 4; n8++) {
            float* d = acc[mt][n8];
            float2 l01 = __half22float2(*(__half2*)&accl[mt][n8][0]);
            float2 l23 = __half22float2(*(__half2*)&accl[mt][n8][1]);
            *(float2*)(C + (size_t)(row0 + mt * 16)     * EMB + col0 + n8 * 8) =
                make_float2(d[0] + l01.x, d[1] + l01.y);
            *(float2*)(C + (size_t)(row0 + mt * 16 + 8) * EMB + col0 + n8 * 8) =
                make_float2(d[2] + l23.x, d[3] + l23.y);
        }
}

// ------- fused diff-attention: rotary + scores + softmax + RMS + pack ------
__global__ __launch_bounds__(128)
void diffattn_kernel(const float* __restrict__ lnw, const float* __restrict__ lnb,
                     __half* __restrict__ outp) {
    __shared__ __align__(16) float sq[1024];
    __shared__ __align__(16) float sk[1024];
    __shared__ __align__(16) float sv[1024];
    __shared__ float saw[2][64];

    int t = blockIdx.x;
    int tid = threadIdx.x;
    int pos = t & (SEQ - 1);

    const float4* gq = (const float4*)(g_q + (size_t)t * EMB);
    const float4* gk = (const float4*)(g_k + (size_t)t * EMB);
    const float4* gv = (const float4*)(g_v + (size_t)t * EMB);
#pragma unroll
    for (int r = 0; r < 2; r++) {
        int i = tid + 128 * r;              // float4 index: dims 4i..4i+3
        int j0 = (2 * i) & 31;              // even, j1 = j0+1
        float4 cs4 = *(const float4*)&g_cs[pos * 32 + j0];  // {c0,s0,c1,s1}
        float4 vq = gq[i], vk = gk[i];
        float4 oq, ok;
        oq.x = vq.x * cs4.x - vq.y * cs4.y;  oq.y = vq.y * cs4.x + vq.x * cs4.y;
        oq.z = vq.z * cs4.z - vq.w * cs4.w;  oq.w = vq.w * cs4.z + vq.z * cs4.w;
        ok.x = vk.x * cs4.x - vk.y * cs4.y;  ok.y = vk.y * cs4.x + vk.x * cs4.y;
        ok.z = vk.z * cs4.z - vk.w * cs4.w;  ok.w = vk.w * cs4.z + vk.z * cs4.w;
        ((float4*)sq)[i] = oq;
        ((float4*)sk)[i] = ok;
        ((float4*)sv)[i] = gv[i];
    }
    __syncthreads();

    {
        int sub = tid >> 6;
        int n   = (tid >> 3) & 7;
        int m   = tid & 7;
        const float* qrow = sq + n * 128 + sub * 64;
        const float* krow = sk + m * 128 + sub * 64;
        float s = 0.0f;
#pragma unroll
        for (int d4 = 0; d4 < 16; d4++) {
            float4 q4 = *(const float4*)(qrow + 4 * d4);
            float4 k4 = *(const float4*)(krow + 4 * d4);
            s += q4.x * k4.x + q4.y * k4.y + q4.z * k4.z + q4.w * k4.w;
        }
        s *= 0.35355339059327376f;
        float mx = s;
        mx = fmaxf(mx, __shfl_xor_sync(0xffffffffu, mx, 1));
        mx = fmaxf(mx, __shfl_xor_sync(0xffffffffu, mx, 2));
        mx = fmaxf(mx, __shfl_xor_sync(0xffffffffu, mx, 4));
        float p = expf(s - mx);
        float sum = p;
        sum += __shfl_xor_sync(0xffffffffu, sum, 1);
        sum += __shfl_xor_sync(0xffffffffu, sum, 2);
        sum += __shfl_xor_sync(0xffffffffu, sum, 4);
        saw[sub][n * 8 + m] = p / sum;
    }
    __syncthreads();

    int n   = tid >> 4;
    int off = (tid & 15) * 8;
    float lam = g_lam;
    float o1[8] = {0,0,0,0,0,0,0,0}, o2[8] = {0,0,0,0,0,0,0,0};
#pragma unroll
    for (int m = 0; m < 8; m++) {
        float w1 = saw[0][n * 8 + m];
        float w2 = saw[1][n * 8 + m];
        float4 va = *(const float4*)&sv[m * 128 + off];
        float4 vb = *(const float4*)&sv[m * 128 + off + 4];
        o1[0] += w1 * va.x; o1[1] += w1 * va.y; o1[2] += w1 * va.z; o1[3] += w1 * va.w;
        o1[4] += w1 * vb.x; o1[5] += w1 * vb.y; o1[6] += w1 * vb.z; o1[7] += w1 * vb.w;
        o2[0] += w2 * va.x; o2[1] += w2 * va.y; o2[2] += w2 * va.z; o2[3] += w2 * va.w;
        o2[4] += w2 * vb.x; o2[5] += w2 * vb.y; o2[6] += w2 * vb.z; o2[7] += w2 * vb.w;
    }
    float a[8];
#pragma unroll
    for (int u = 0; u < 8; u++) a[u] = o1[u] - lam * o2[u];

    float ss = 0.0f;
#pragma unroll
    for (int u = 0; u < 8; u++) ss += a[u] * a[u];
    ss += __shfl_xor_sync(0xffffffffu, ss, 1);
    ss += __shfl_xor_sync(0xffffffffu, ss, 2);
    ss += __shfl_xor_sync(0xffffffffu, ss, 4);
    ss += __shfl_xor_sync(0xffffffffu, ss, 8);
    float rms = rsqrtf(ss * (1.0f / 128.0f) + 1e-8f);

    const float LIC = 0.21639423346837556f;  // 1 - LAMBDA_INIT
    float vals[8];
#pragma unroll
    for (int u = 0; u < 8; u++)
        vals[u] = (a[u] * rms * lnw[off + u] + lnb[off + u]) * LIC;

    uint4 hv = pack8_hi(vals);
    int e0w = n * 128 + off;
    int tile = t >> 7, r = t & 127;
    int kc = e0w >> 5, c4 = (e0w >> 3) & 3, p = c4 ^ ((r >> 1) & 3);
    size_t base = (size_t)(tile * 32 + kc) * 8192 + (size_t)r * 64 + p * 16;
    *(uint4*)((char*)outp + base) = hv;
}

// ---------------- launch ----------------------------------------------------
extern "C" void kernel_launch(void* const* d_in, const int* in_sizes, int n_in,
                              void* d_out, int out_size) {
    const float* x   = (const float*)d_in[0];
    const float* Wq  = (const float*)d_in[1];
    const float* Wk  = (const float*)d_in[2];
    const float* Wv  = (const float*)d_in[3];
    const float* Wo  = (const float*)d_in[4];
    const float* lq1 = (const float*)d_in[5];
    const float* lk1 = (const float*)d_in[6];
    const float* lq2 = (const float*)d_in[7];
    const float* lk2 = (const float*)d_in[8];
    const float* lnw = (const float*)d_in[9];
    const float* lnb = (const float*)d_in[10];
    float* out = (float*)d_out;

    float *q, *k, *v;
    __half *xs, *as, *ws;
    cudaGetSymbolAddress((void**)&q,  g_q);
    cudaGetSymbolAddress((void**)&k,  g_k);
    cudaGetSymbolAddress((void**)&v,  g_v);
    cudaGetSymbolAddress((void**)&xs, g_xs);
    cudaGetSymbolAddress((void**)&as, g_as);
    cudaGetSymbolAddress((void**)&ws, g_ws);

    cudaFuncSetAttribute(gemm_hmma, cudaFuncAttributeMaxDynamicSharedMemorySize, SMEM_DYN);

    // 1: merged prep (split_x + rope table + lambda)
    prep_kernel<<<TOKENS * 128 / 256, 256>>>(x, xs, lq1, lk1, lq2, lk2);
    // 2: weight transpose+split (all four matrices)
    wsplit4_kernel<<<dim3(32, 32, 4), 128>>>(Wq, Wk, Wv, Wo, ws);

    // 3: fused QKV GEMM (z selects weight + destination)
    dim3 g3(EMB / 128, TOKENS / 128, 3);
    gemm_hmma<<<g3, 256, SMEM_DYN>>>(xs, ws, q, k, v);

    // 4: fused rotary + diff-attention + RMSNorm + fp16 pack
    diffattn_kernel<<<TOKENS, 128>>>(lnw, lnb, as);

    // 5: output projection
    dim3 g1(EMB / 128, TOKENS / 128, 1);
    gemm_hmma<<<g1, 256, SMEM_DYN>>>(as, ws + 3ull * 2 * EMB * EMB, out, out, out);
}